// round 11
// baseline (speedup 1.0000x reference)
#include <cuda_runtime.h>
#include <cuda_bf16.h>
#include <math.h>
#include <stdint.h>

#define NN 50000
#define MPAD 50048            // 391 * 128, padded row count for GEMM A operands
#define EE 800000
#define DD 256
#define HID 1024
#define STEPS 6

// ---------------- scratch (device globals; no runtime allocation) -------------
__device__ int   g_deg[NN];
__device__ int   g_tmp[NN];
__device__ int   g_rowptr[NN + 1];
__device__ int   g_srcs[EE];
__device__ float g_eas[EE];           // edge_attr, CSR-sorted
__device__ int   g_lts[EE];           // link_type, CSR-sorted
__device__ float g_xd[NN * 8];        // x @ Watt[0:32]
__device__ float g_xs[NN * 8];        // x @ Watt[32:64]
__device__ float g_xlin[NN * 32];     // x @ Wlin[0:32]
__device__ float g_m[NN * DD];        // running node state (fp32)
__device__ float g_f[NN * DD];        // FFN out scratch
// packed bf16 hi/lo operands (pair-packed [row][k/2] uint32, K-major)
__device__ uint32_t g_mah[MPAD * (DD / 2)];   // m (GEMM1 A) hi
__device__ uint32_t g_mal[MPAD * (DD / 2)];   // m lo
__device__ uint32_t g_hh[MPAD * (HID / 2)];   // hidden (GEMM2 A) hi
__device__ uint32_t g_hl[MPAD * (HID / 2)];   // hidden lo
// rank-1 edge-constant tables (leaky is positively homogeneous in scalar ea)
__device__ float g_cvp[32], g_cvn[32];   // message vec for a>0 / a<0
__device__ float g_avp[8],  g_avn[8];    // attention vec for a>0 / a<0
__device__ float g_ete[3 * 8];           // link-type attention table
// pre-split FFN weights: bf16 hi/lo, TRANSPOSED [n][k/2] pair-packed layout
__device__ uint32_t g_w1h[STEPS * HID * (DD / 2)];
__device__ uint32_t g_w1l[STEPS * HID * (DD / 2)];
__device__ uint32_t g_w2h[STEPS * DD * (HID / 2)];
__device__ uint32_t g_w2l[STEPS * DD * (HID / 2)];

// ---------------- bf16 split helpers -------------------------------------------
__device__ __forceinline__ float bf16_hi(float x) {
    return __bfloat162float(__float2bfloat16(x));
}
__device__ __forceinline__ uint32_t pack2(float lo_elem, float hi_elem) {
    __nv_bfloat162 p = __floats2bfloat162_rn(lo_elem, hi_elem);  // .x = low 16 bits
    return *reinterpret_cast<uint32_t*>(&p);
}

// ---------------- preprocessing ------------------------------------------------
__global__ void zero_kernel() {
    int i = blockIdx.x * blockDim.x + threadIdx.x;
    if (i < NN) { g_deg[i] = 0; g_tmp[i] = 0; }
}

__global__ void hist_kernel(const int* __restrict__ dst) {
    int e = blockIdx.x * blockDim.x + threadIdx.x;
    if (e < EE) atomicAdd(&g_deg[dst[e]], 1);
}

__global__ void scan_kernel() {
    __shared__ int ws[32];
    __shared__ int carry_s;
    int tid = threadIdx.x, lane = tid & 31, wid = tid >> 5;
    if (tid == 0) carry_s = 0;
    __syncthreads();
    for (int base = 0; base < NN; base += 1024) {
        int i = base + tid;
        int v = (i < NN) ? g_deg[i] : 0;
        int x = v;
        #pragma unroll
        for (int o = 1; o < 32; o <<= 1) {
            int y = __shfl_up_sync(0xffffffffu, x, o);
            if (lane >= o) x += y;
        }
        if (lane == 31) ws[wid] = x;
        __syncthreads();
        if (tid < 32) {
            int w = ws[tid];
            #pragma unroll
            for (int o = 1; o < 32; o <<= 1) {
                int y = __shfl_up_sync(0xffffffffu, w, o);
                if (tid >= o) w += y;
            }
            ws[tid] = w;
        }
        __syncthreads();
        int incl = x + (wid > 0 ? ws[wid - 1] : 0);
        int carry = carry_s;
        if (i < NN) g_rowptr[i] = carry + incl - v;  // exclusive
        __syncthreads();
        if (tid == 1023) carry_s = carry + incl;
        __syncthreads();
    }
    if (tid == 0) g_rowptr[NN] = carry_s;
}

// CSR scatter: also gather per-edge scalars (edge_attr, link_type) directly
__global__ void scatter_kernel(const int* __restrict__ src, const int* __restrict__ dst,
                               const float* __restrict__ ea, const int* __restrict__ ltype) {
    int e = blockIdx.x * blockDim.x + threadIdx.x;
    if (e >= EE) return;
    int d = dst[e];
    int r = atomicAdd(&g_tmp[d], 1);
    int pos = g_rowptr[d] + r;
    g_srcs[pos] = src[e];
    g_eas[pos]  = ea[e];
    g_lts[pos]  = ltype[e];
}

// rank-1 edge-constant tables
__global__ void prep_tables_kernel(const float* __restrict__ Wea,
                                   const float* __restrict__ Watt,
                                   const float* __restrict__ Et,
                                   const float* __restrict__ Wlin) {
    int lane = threadIdx.x;  // one warp
    float cp = 0.f, cn = 0.f;
    #pragma unroll
    for (int j = 0; j < 50; j++) {
        float w = Wea[j];
        float lp = w > 0.f ? w : 0.2f * w;
        float ln_ = w > 0.f ? 0.2f * w : w;
        float wl = Wlin[(32 + j) * 32 + lane];
        cp = fmaf(lp, wl, cp);
        cn = fmaf(ln_, wl, cn);
    }
    g_cvp[lane] = cp; g_cvn[lane] = cn;
    if (lane < 8) {
        float ap = 0.f, an = 0.f;
        #pragma unroll
        for (int j = 0; j < 50; j++) {
            float w = Wea[j];
            float lp = w > 0.f ? w : 0.2f * w;
            float ln_ = w > 0.f ? 0.2f * w : w;
            float wa = Watt[(74 + j) * 8 + lane];
            ap = fmaf(lp, wa, ap);
            an = fmaf(ln_, wa, an);
        }
        g_avp[lane] = ap; g_avn[lane] = an;
        #pragma unroll
        for (int lt = 0; lt < 3; lt++) {
            float s = 0.f;
            #pragma unroll
            for (int j = 0; j < 10; j++) {
                float t = Et[lt * 10 + j];
                t = t > 0.f ? t : 0.2f * t;
                s = fmaf(t, Watt[(64 + j) * 8 + lane], s);
            }
            g_ete[lt * 8 + lane] = s;
        }
    }
}

// split both FFN weight tensors into bf16 hi/lo, transposed [n][k/2]-pair layout.
__global__ void split_w_kernel(const float* __restrict__ w1, const float* __restrict__ w2) {
    int i = blockIdx.x * blockDim.x + threadIdx.x;
    const int n1 = STEPS * HID * (DD / 2);
    if (i >= n1) return;
    {
        int s = i / (HID * (DD / 2));
        int rem = i % (HID * (DD / 2));
        int n = rem / (DD / 2);
        int kp = rem % (DD / 2);
        const float* base = w1 + (size_t)s * DD * HID;
        float b0 = base[(size_t)(2 * kp) * HID + n];
        float b1 = base[(size_t)(2 * kp + 1) * HID + n];
        float h0 = bf16_hi(b0), h1 = bf16_hi(b1);
        g_w1h[i] = pack2(h0, h1);
        g_w1l[i] = pack2(b0 - h0, b1 - h1);
    }
    {
        int s = i / (DD * (HID / 2));
        int rem = i % (DD * (HID / 2));
        int n = rem / (HID / 2);
        int kp = rem % (HID / 2);
        const float* base = w2 + (size_t)s * HID * DD;
        float b0 = base[(size_t)(2 * kp) * DD + n];
        float b1 = base[(size_t)(2 * kp + 1) * DD + n];
        float h0 = bf16_hi(b0), h1 = bf16_hi(b1);
        g_w2h[i] = pack2(h0, h1);
        g_w2l[i] = pack2(b0 - h0, b1 - h1);
    }
}

// -------------- per-step: HeteroLinear + fused projections ---------------------
__global__ void hetero_kernel(const int* __restrict__ ntype,
                              const float* __restrict__ Wh, const float* __restrict__ bh,
                              const float* __restrict__ Watt, const float* __restrict__ Wlin) {
    int warp = (blockIdx.x * blockDim.x + threadIdx.x) >> 5;
    int lane = threadIdx.x & 31;
    int n0 = warp * 4;
    if (n0 >= NN) return;
    float acc0[4] = {0.f, 0.f, 0.f, 0.f};
    float acc1[4] = {0.f, 0.f, 0.f, 0.f};
    for (int j = 0; j < DD; j += 4) {
        float mv[4][4];
        #pragma unroll
        for (int q = 0; q < 4; q++) {
            int n = n0 + q;
            float4 t = (n < NN) ? *(const float4*)(g_m + (size_t)n * DD + j)
                                : make_float4(0.f, 0.f, 0.f, 0.f);
            mv[q][0] = t.x; mv[q][1] = t.y; mv[q][2] = t.z; mv[q][3] = t.w;
        }
        #pragma unroll
        for (int jj = 0; jj < 4; jj++) {
            float w0 = Wh[(j + jj) * 32 + lane];
            float w1 = Wh[DD * 32 + (j + jj) * 32 + lane];
            #pragma unroll
            for (int q = 0; q < 4; q++) {
                acc0[q] = fmaf(mv[q][jj], w0, acc0[q]);
                acc1[q] = fmaf(mv[q][jj], w1, acc1[q]);
            }
        }
    }
    for (int q = 0; q < 4; q++) {
        int n = n0 + q;
        if (n >= NN) break;
        int t = ntype[n];
        float xv = (t == 0 ? acc0[q] : acc1[q]) + bh[t * 32 + lane];
        #pragma unroll
        for (int h = 0; h < 8; h++) {
            float pd = xv * Watt[lane * 8 + h];
            float ps = xv * Watt[(32 + lane) * 8 + h];
            #pragma unroll
            for (int o = 16; o > 0; o >>= 1) {
                pd += __shfl_xor_sync(0xffffffffu, pd, o);
                ps += __shfl_xor_sync(0xffffffffu, ps, o);
            }
            if (lane == 0) { g_xd[n * 8 + h] = pd; g_xs[n * 8 + h] = ps; }
        }
        float xl = 0.f;
        #pragma unroll
        for (int c = 0; c < 32; c++) {
            float xb = __shfl_sync(0xffffffffu, xv, c);
            xl = fmaf(xb, Wlin[c * 32 + lane], xl);
        }
        g_xlin[n * 32 + lane] = xl;
    }
}

// -------------- per-step: attention + aggregation + fused LayerNorm-1 ----------
// Also emits the new m row as packed bf16 hi/lo pairs (GEMM1 A operand).
__global__ void att_ln_kernel(const float* __restrict__ gg, const float* __restrict__ bb) {
    int node = (blockIdx.x * blockDim.x + threadIdx.x) >> 5;
    if (node >= NN) return;
    int lane = threadIdx.x & 31;
    int start = g_rowptr[node], end = g_rowptr[node + 1];
    int h = lane & 7, eo = lane >> 3;
    float xd  = g_xd[node * 8 + h];
    float avp = g_avp[h], avn = g_avn[h];
    float e0 = g_ete[h], e1 = g_ete[8 + h], e2 = g_ete[16 + h];
    float mx = -INFINITY;
    for (int base = start; base < end; base += 4) {
        int pos = base + eo;
        float l = -INFINITY;
        if (pos < end) {
            int s = g_srcs[pos];
            float a = g_eas[pos];
            int lt = g_lts[pos];
            float et = (lt == 0) ? e0 : ((lt == 1) ? e1 : e2);
            float v = xd + g_xs[s * 8 + h] + et + a * (a > 0.f ? avp : avn);
            l = v > 0.f ? v : 0.2f * v;
        }
        mx = fmaxf(mx, l);
    }
    mx = fmaxf(mx, __shfl_xor_sync(0xffffffffu, mx, 8));
    mx = fmaxf(mx, __shfl_xor_sync(0xffffffffu, mx, 16));
    float cvp = g_cvp[lane], cvn = g_cvn[lane];
    float ssum = 0.f;
    float acc[8] = {0.f, 0.f, 0.f, 0.f, 0.f, 0.f, 0.f, 0.f};
    for (int pos = start; pos < end; pos++) {
        int s = g_srcs[pos];
        float a = g_eas[pos];
        int lt = g_lts[pos];
        float et = (lt == 0) ? e0 : ((lt == 1) ? e1 : e2);
        float v = xd + g_xs[s * 8 + h] + et + a * (a > 0.f ? avp : avn);
        v = v > 0.f ? v : 0.2f * v;
        float ev = expf(v - mx);
        ssum += ev;
        float msg = g_xlin[s * 32 + lane] + a * (a > 0.f ? cvp : cvn);
        #pragma unroll
        for (int hh = 0; hh < 8; hh++) {
            float aw = __shfl_sync(0xffffffffu, ev, hh);
            acc[hh] = fmaf(aw, msg, acc[hh]);
        }
    }
    float inv = 1.f / (ssum + 1e-16f);
    float vrow[8];
    #pragma unroll
    for (int hh = 0; hh < 8; hh++) {
        float ih = __shfl_sync(0xffffffffu, inv, hh);
        vrow[hh] = acc[hh] * ih + g_m[(size_t)node * DD + hh * 32 + lane];
    }
    float s = 0.f, sq = 0.f;
    #pragma unroll
    for (int i = 0; i < 8; i++) { s += vrow[i]; sq += vrow[i] * vrow[i]; }
    #pragma unroll
    for (int o = 16; o > 0; o >>= 1) {
        s  += __shfl_xor_sync(0xffffffffu, s, o);
        sq += __shfl_xor_sync(0xffffffffu, sq, o);
    }
    float mu = s * (1.0f / DD);
    float var = sq * (1.0f / DD) - mu * mu;
    float rs = rsqrtf(var + 1e-5f);
    #pragma unroll
    for (int hh = 0; hh < 8; hh++) {
        int c = hh * 32 + lane;
        float ov = (vrow[hh] - mu) * rs * gg[c] + bb[c];
        g_m[(size_t)node * DD + c] = ov;
        float ov2 = __shfl_down_sync(0xffffffffu, ov, 1);
        if (!(lane & 1)) {
            float h0 = bf16_hi(ov), h1 = bf16_hi(ov2);
            int pi = hh * 16 + (lane >> 1);
            g_mah[(size_t)node * (DD / 2) + pi] = pack2(h0, h1);
            g_mal[(size_t)node * (DD / 2) + pi] = pack2(ov - h0, ov2 - h1);
        }
    }
}

// -------------- LayerNorm(f + mio) -> mio (warp per row; post-FFN LN2) ---------
__global__ void ln_kernel(const float* __restrict__ f, float* __restrict__ mio,
                          const float* __restrict__ gg, const float* __restrict__ bb) {
    int row = (blockIdx.x * blockDim.x + threadIdx.x) >> 5;
    if (row >= NN) return;
    int lane = threadIdx.x & 31;
    const float4* f4 = (const float4*)(f + (size_t)row * DD);
    const float4* r4 = (const float4*)(mio + (size_t)row * DD);
    float4 a0 = f4[lane * 2], a1 = f4[lane * 2 + 1];
    float4 c0 = r4[lane * 2], c1 = r4[lane * 2 + 1];
    float v[8] = {a0.x + c0.x, a0.y + c0.y, a0.z + c0.z, a0.w + c0.w,
                  a1.x + c1.x, a1.y + c1.y, a1.z + c1.z, a1.w + c1.w};
    float s = 0.f, sq = 0.f;
    #pragma unroll
    for (int i = 0; i < 8; i++) { s += v[i]; sq += v[i] * v[i]; }
    #pragma unroll
    for (int o = 16; o > 0; o >>= 1) {
        s  += __shfl_xor_sync(0xffffffffu, s, o);
        sq += __shfl_xor_sync(0xffffffffu, sq, o);
    }
    float mu = s * (1.0f / DD);
    float var = sq * (1.0f / DD) - mu * mu;
    float rs = rsqrtf(var + 1e-5f);
    int c = lane * 8;
    float o_[8];
    #pragma unroll
    for (int i = 0; i < 8; i++) o_[i] = (v[i] - mu) * rs * gg[c + i] + bb[c + i];
    float4* w4 = (float4*)(mio + (size_t)row * DD);
    w4[lane * 2]     = make_float4(o_[0], o_[1], o_[2], o_[3]);
    w4[lane * 2 + 1] = make_float4(o_[4], o_[5], o_[6], o_[7]);
}

// ============ bf16x3 GEMM, all operands pre-split, cp.async pipelined ==========
// C = A @ B + bias. A: [MPAD][K/2] packed hi/lo. B: [N][K/2] packed hi/lo.
// D += Ahi*Bhi + Ahi*Blo + Alo*Bhi (mma.sync m16n8k16 bf16).
// 2-stage cp.async smem ring; stage = 4 arrays x 128 rows x 20 words (16 used).
// packed_out: emit C as packed bf16 hi/lo (for next GEMM's A) instead of fp32.
__device__ __forceinline__ void mma_bf16(float* d, const uint32_t* a, const uint32_t* b) {
    asm volatile(
        "mma.sync.aligned.m16n8k16.row.col.f32.bf16.bf16.f32 "
        "{%0,%1,%2,%3}, {%4,%5,%6,%7}, {%8,%9}, {%0,%1,%2,%3};\n"
        : "+f"(d[0]), "+f"(d[1]), "+f"(d[2]), "+f"(d[3])
        : "r"(a[0]), "r"(a[1]), "r"(a[2]), "r"(a[3]), "r"(b[0]), "r"(b[1]));
}
__device__ __forceinline__ uint32_t smem_u32(const void* p) {
    uint32_t a;
    asm("{ .reg .u64 t; cvta.to.shared.u64 t, %1; cvt.u32.u64 %0, t; }"
        : "=r"(a) : "l"(p));
    return a;
}
__device__ __forceinline__ void cp16(uint32_t dst, const void* src) {
    asm volatile("cp.async.cg.shared.global [%0], [%1], 16;" :: "r"(dst), "l"(src));
}

#define STG_W 10240                 // words per stage (4 arrays x 128 x 20)
#define ARR_W 2560                  // words per array
#define PIPE_SMEM (2 * STG_W * 4)   // 81920 bytes

__global__ void __launch_bounds__(256, 2)
pp_gemm_kernel(int M, int Nn, int K,
               const uint32_t* __restrict__ Ahp, const uint32_t* __restrict__ Alp,
               const uint32_t* __restrict__ Bhp, const uint32_t* __restrict__ Blp,
               const float* __restrict__ bias,
               float* __restrict__ C, uint32_t* __restrict__ Chp, uint32_t* __restrict__ Clp,
               int relu, int packed_out) {
    extern __shared__ uint32_t sm[];
    uint32_t sb = smem_u32(sm);
    int tid = threadIdx.x, lane = tid & 31, wid = tid >> 5;
    int wm = wid >> 2, wn = wid & 3;
    int g = lane >> 2, t = lane & 3;
    int row0 = blockIdx.y * 128, col0 = blockIdx.x * 128;
    int Kh = K >> 1;

    float acc[4][4][4];
    #pragma unroll
    for (int i = 0; i < 4; i++)
        #pragma unroll
        for (int j = 0; j < 4; j++)
            #pragma unroll
            for (int r = 0; r < 4; r++) acc[i][j][r] = 0.f;

    int nchunks = K >> 5;   // 32 K-elems (16 pairs) per chunk
    // per-thread copy coords
    int cr = tid >> 1;                 // not used; real mapping below

    // ---- issue stage 0 ----
    {
        uint32_t base = sb;
        #pragma unroll
        for (int i = 0; i < 2; i++) {
            int q = tid + 256 * i;
            int r = q >> 2, c4 = q & 3;
            size_t soA = (size_t)(row0 + r) * Kh + c4 * 4;
            size_t soB = (size_t)(col0 + r) * Kh + c4 * 4;
            uint32_t d = base + (uint32_t)(r * 20 + c4 * 4) * 4;
            cp16(d,                Ahp + soA);
            cp16(d + ARR_W * 4,     Alp + soA);
            cp16(d + 2 * ARR_W * 4, Bhp + soB);
            cp16(d + 3 * ARR_W * 4, Blp + soB);
        }
        asm volatile("cp.async.commit_group;" ::: "memory");
    }

    for (int kc = 0; kc < nchunks; kc++) {
        bool more = (kc + 1) < nchunks;
        if (more) {
            uint32_t base = sb + (uint32_t)(((kc + 1) & 1) * STG_W) * 4;
            int ko = (kc + 1) * 16;
            #pragma unroll
            for (int i = 0; i < 2; i++) {
                int q = tid + 256 * i;
                int r = q >> 2, c4 = q & 3;
                size_t soA = (size_t)(row0 + r) * Kh + ko + c4 * 4;
                size_t soB = (size_t)(col0 + r) * Kh + ko + c4 * 4;
                uint32_t d = base + (uint32_t)(r * 20 + c4 * 4) * 4;
                cp16(d,                Ahp + soA);
                cp16(d + ARR_W * 4,     Alp + soA);
                cp16(d + 2 * ARR_W * 4, Bhp + soB);
                cp16(d + 3 * ARR_W * 4, Blp + soB);
            }
            asm volatile("cp.async.commit_group;" ::: "memory");
            asm volatile("cp.async.wait_group 1;" ::: "memory");
        } else {
            asm volatile("cp.async.wait_group 0;" ::: "memory");
        }
        __syncthreads();

        const uint32_t* Ahs = sm + (kc & 1) * STG_W;
        const uint32_t* Als = Ahs + ARR_W;
        const uint32_t* Bhs = Ahs + 2 * ARR_W;
        const uint32_t* Bls = Ahs + 3 * ARR_W;

        #pragma unroll
        for (int kp = 0; kp < 16; kp += 8) {
            uint32_t bhf[4][2], blf[4][2];
            #pragma unroll
            for (int nj = 0; nj < 4; nj++) {
                int n = wn * 32 + nj * 8 + g;
                bhf[nj][0] = Bhs[n * 20 + kp + t];
                bhf[nj][1] = Bhs[n * 20 + kp + t + 4];
                blf[nj][0] = Bls[n * 20 + kp + t];
                blf[nj][1] = Bls[n * 20 + kp + t + 4];
            }
            #pragma unroll
            for (int mi = 0; mi < 4; mi++) {
                int m = wm * 64 + mi * 16;
                uint32_t ahf[4], alf[4];
                ahf[0] = Ahs[(m + g) * 20 + kp + t];
                ahf[1] = Ahs[(m + g + 8) * 20 + kp + t];
                ahf[2] = Ahs[(m + g) * 20 + kp + t + 4];
                ahf[3] = Ahs[(m + g + 8) * 20 + kp + t + 4];
                alf[0] = Als[(m + g) * 20 + kp + t];
                alf[1] = Als[(m + g + 8) * 20 + kp + t];
                alf[2] = Als[(m + g) * 20 + kp + t + 4];
                alf[3] = Als[(m + g + 8) * 20 + kp + t + 4];
                #pragma unroll
                for (int nj = 0; nj < 4; nj++) {
                    mma_bf16(acc[mi][nj], ahf, bhf[nj]);   // hi*hi
                    mma_bf16(acc[mi][nj], ahf, blf[nj]);   // hi*lo
                    mma_bf16(acc[mi][nj], alf, bhf[nj]);   // lo*hi
                }
            }
        }
        __syncthreads();
    }

    // epilogue: c0 (row g, col 2t), c1 (row g, 2t+1), c2 (row g+8, 2t), c3 (g+8, 2t+1)
    int Nh = Nn >> 1;
    #pragma unroll
    for (int nj = 0; nj < 4; nj++) {
        int cb = col0 + wn * 32 + nj * 8 + 2 * t;
        float b0 = bias[cb], b1 = bias[cb + 1];
        #pragma unroll
        for (int mi = 0; mi < 4; mi++) {
            int r0 = row0 + wm * 64 + mi * 16 + g;
            float v0 = acc[mi][nj][0] + b0;
            float v1 = acc[mi][nj][1] + b1;
            float v2 = acc[mi][nj][2] + b0;
            float v3 = acc[mi][nj][3] + b1;
            if (relu) {
                v0 = fmaxf(v0, 0.f); v1 = fmaxf(v1, 0.f);
                v2 = fmaxf(v2, 0.f); v3 = fmaxf(v3, 0.f);
            }
            if (packed_out) {
                if (r0 < M) {
                    float h0 = bf16_hi(v0), h1 = bf16_hi(v1);
                    size_t idx = (size_t)r0 * Nh + (cb >> 1);
                    Chp[idx] = pack2(h0, h1);
                    Clp[idx] = pack2(v0 - h0, v1 - h1);
                }
                if (r0 + 8 < M) {
                    float h2 = bf16_hi(v2), h3 = bf16_hi(v3);
                    size_t idx = (size_t)(r0 + 8) * Nh + (cb >> 1);
                    Chp[idx] = pack2(h2, h3);
                    Clp[idx] = pack2(v2 - h2, v3 - h3);
                }
            } else {
                if (r0 < M) {
                    C[(size_t)r0 * Nn + cb]     = v0;
                    C[(size_t)r0 * Nn + cb + 1] = v1;
                }
                if (r0 + 8 < M) {
                    C[(size_t)(r0 + 8) * Nn + cb]     = v2;
                    C[(size_t)(r0 + 8) * Nn + cb + 1] = v3;
                }
            }
        }
    }
}

// -------------------------------- launcher -------------------------------------
extern "C" void kernel_launch(void* const* d_in, const int* in_sizes, int n_in,
                              void* d_out, int out_size) {
    const float* x     = (const float*)d_in[0];
    const int*   ei    = (const int*)  d_in[1];
    const float* ea    = (const float*)d_in[2];
    const int*   ntype = (const int*)  d_in[3];
    const int*   ltype = (const int*)  d_in[4];
    const float* Wh    = (const float*)d_in[5];
    const float* bh    = (const float*)d_in[6];
    const float* Et    = (const float*)d_in[7];
    const float* Wea   = (const float*)d_in[8];
    const float* Watt  = (const float*)d_in[9];
    const float* Wlin  = (const float*)d_in[10];
    const float* w1    = (const float*)d_in[11];
    const float* b1    = (const float*)d_in[12];
    const float* w2    = (const float*)d_in[13];
    const float* b2    = (const float*)d_in[14];
    const float* ln1g  = (const float*)d_in[15];
    const float* ln1b  = (const float*)d_in[16];
    const float* ln2g  = (const float*)d_in[17];
    const float* ln2b  = (const float*)d_in[18];
    const int* srcp = ei;
    const int* dstp = ei + EE;

    cudaFuncSetAttribute(pp_gemm_kernel,
                         cudaFuncAttributeMaxDynamicSharedMemorySize, PIPE_SMEM);

    void *pm, *pf, *pmah, *pmal, *phh, *phl, *pw1h, *pw1l, *pw2h, *pw2l;
    cudaGetSymbolAddress(&pm, g_m);
    cudaGetSymbolAddress(&pf, g_f);
    cudaGetSymbolAddress(&pmah, g_mah);
    cudaGetSymbolAddress(&pmal, g_mal);
    cudaGetSymbolAddress(&phh, g_hh);
    cudaGetSymbolAddress(&phl, g_hl);
    cudaGetSymbolAddress(&pw1h, g_w1h);
    cudaGetSymbolAddress(&pw1l, g_w1l);
    cudaGetSymbolAddress(&pw2h, g_w2h);
    cudaGetSymbolAddress(&pw2l, g_w2l);
    float* m_ptr = (float*)pm;
    float* f_ptr = (float*)pf;
    uint32_t* mah = (uint32_t*)pmah;
    uint32_t* mal = (uint32_t*)pmal;
    uint32_t* hh_ = (uint32_t*)phh;
    uint32_t* hl_ = (uint32_t*)phl;
    const uint32_t* w1h = (const uint32_t*)pw1h;
    const uint32_t* w1l = (const uint32_t*)pw1l;
    const uint32_t* w2h = (const uint32_t*)pw2h;
    const uint32_t* w2l = (const uint32_t*)pw2l;

    // ---- per-launch preprocessing (step-invariant) ----
    zero_kernel<<<(NN + 255) / 256, 256>>>();
    hist_kernel<<<(EE + 255) / 256, 256>>>(dstp);
    scan_kernel<<<1, 1024>>>();
    scatter_kernel<<<(EE + 255) / 256, 256>>>(srcp, dstp, ea, ltype);
    prep_tables_kernel<<<1, 32>>>(Wea, Watt, Et, Wlin);
    split_w_kernel<<<(STEPS * HID * (DD / 2) + 255) / 256, 256>>>(w1, w2);
    cudaMemcpyAsync(m_ptr, x, (size_t)NN * DD * sizeof(float),
                    cudaMemcpyDeviceToDevice, 0);

    int hetero_blocks = (((NN + 3) / 4) * 32 + 255) / 256;
    int warpN_blocks  = (NN * 32 + 255) / 256;
    dim3 gg1(HID / 128, MPAD / 128);
    dim3 gg2(DD / 128, MPAD / 128);

    for (int s = 0; s < STEPS; s++) {
        hetero_kernel<<<hetero_blocks, 256>>>(ntype, Wh, bh, Watt, Wlin);
        att_ln_kernel<<<warpN_blocks, 256>>>(ln1g + s * DD, ln1b + s * DD);
        pp_gemm_kernel<<<gg1, 256, PIPE_SMEM>>>(NN, HID, DD, mah, mal,
                                      w1h + (size_t)s * HID * (DD / 2),
                                      w1l + (size_t)s * HID * (DD / 2),
                                      b1 + (size_t)s * HID,
                                      (float*)0, hh_, hl_, 1, 1);
        pp_gemm_kernel<<<gg2, 256, PIPE_SMEM>>>(NN, DD, HID, hh_, hl_,
                                      w2h + (size_t)s * DD * (HID / 2),
                                      w2l + (size_t)s * DD * (HID / 2),
                                      b2 + (size_t)s * DD,
                                      f_ptr, (uint32_t*)0, (uint32_t*)0, 0, 0);
        ln_kernel<<<warpN_blocks, 256>>>(f_ptr, m_ptr, ln2g + s * DD, ln2b + s * DD);
    }
    cudaMemcpyAsync(d_out, m_ptr, (size_t)NN * DD * sizeof(float),
                    cudaMemcpyDeviceToDevice, 0);
}